// round 6
// baseline (speedup 1.0000x reference)
#include <cuda_runtime.h>
#include <math.h>

// ---------------------------------------------------------------------------
// Problem constants: B=2, S=2048, DIM=2048, H=16, HDIM=128
// ---------------------------------------------------------------------------
#define DIMV 2048
#define GM   4096      // B*S rows
#define SEQ  2048
#define NHEAD 16
#define HDIM 128

// Scratch (device globals: allocation-free per harness rules)
__device__ float g_qr [GM * DIMV];          // rope'd + scaled + tf32 q
__device__ float g_kr [GM * DIMV];          // rope'd + tf32 k
__device__ float g_v  [GM * DIMV];          // tf32 v
__device__ float g_att[GM * DIMV];
__device__ float g_xr [GM * DIMV];          // tf32-rounded x
__device__ float g_wqr[DIMV * DIMV];        // tf32-rounded weights
__device__ float g_wkr[DIMV * DIMV];
__device__ float g_wvr[DIMV * DIMV];
__device__ float g_wor[DIMV * DIMV];
__device__ float g_tcos[SEQ * 64];
__device__ float g_tsin[SEQ * 64];
__device__ float g_invf[64];

// ---------------------------------------------------------------------------
// Helpers
// ---------------------------------------------------------------------------
__device__ __forceinline__ float tf32r(float x) {
    unsigned u;
    asm("cvt.rna.tf32.f32 %0, %1;" : "=r"(u) : "f"(x));
    return __uint_as_float(u);
}

__device__ __forceinline__ unsigned smem_u32(const void* p) {
    return (unsigned)__cvta_generic_to_shared(p);
}

#define CP_ASYNC16(dst_u32, src) \
    asm volatile("cp.async.cg.shared.global [%0], [%1], 16;\n" :: "r"(dst_u32), "l"(src))
#define CP_COMMIT() asm volatile("cp.async.commit_group;\n" ::)
#define CP_WAIT1()  asm volatile("cp.async.wait_group 1;\n" ::)
#define CP_WAIT0()  asm volatile("cp.async.wait_group 0;\n" ::)

// mma.sync m16n8k8 tf32 fp32-accum (row.col).
// Frag layout (g=lane>>2, c=lane&3):
//   A: a0=(g,c) a1=(g+8,c) a2=(g,c+4) a3=(g+8,c+4)       [A is m x k]
//   B: b0=(k=c,n=g) b1=(k=c+4,n=g)                        [B is k x n]
//   C: c0=(g,2c) c1=(g,2c+1) c2=(g+8,2c) c3=(g+8,2c+1)
__device__ __forceinline__ void mma8(float* d, const float* a, const float* b) {
    asm volatile(
        "mma.sync.aligned.m16n8k8.row.col.f32.tf32.tf32.f32 "
        "{%0,%1,%2,%3}, {%4,%5,%6,%7}, {%8,%9}, {%0,%1,%2,%3};\n"
        : "+f"(d[0]), "+f"(d[1]), "+f"(d[2]), "+f"(d[3])
        : "r"(__float_as_uint(a[0])), "r"(__float_as_uint(a[1])),
          "r"(__float_as_uint(a[2])), "r"(__float_as_uint(a[3])),
          "r"(__float_as_uint(b[0])), "r"(__float_as_uint(b[1])));
}

// ---------------------------------------------------------------------------
// tf32 pre-round pass (float4 vectorized)
// ---------------------------------------------------------------------------
__global__ void round_copy(const float* __restrict__ src, float* __restrict__ dst,
                           int n4) {
    int i = blockIdx.x * blockDim.x + threadIdx.x;
    if (i >= n4) return;
    float4 v = ((const float4*)src)[i];
    v.x = tf32r(v.x); v.y = tf32r(v.y); v.z = tf32r(v.z); v.w = tf32r(v.w);
    ((float4*)dst)[i] = v;
}

// ---------------------------------------------------------------------------
// GEMM (NT): C[4096,2048] = A[4096,2048] * W[2048,2048]^T, inputs pre-rounded.
// 128x128x32 block tile, 256 threads (2x4 warps), warp tile 64x32.
// cp.async 2-stage pipeline. Smem stride 36 (==4 mod 32): frag loads hit
// banks (4g+c) -> conflict-free.
//
// MODE epilogues (block covers cols [nbase,nbase+128) == exactly one head):
//   0: plain fp32 store (Wo output)
//   1: RoPE + 1/sqrt(128) scale + tf32 round (Q)
//   2: RoPE + tf32 round (K)
//   3: tf32 round (V)
// RoPE modes round-trip the acc tile through the (now dead) pipeline smem.
// ---------------------------------------------------------------------------
#define GSTR 36
#define GEMM_STAGE (128 * GSTR)           // floats per matrix per stage
#define GEMM_SMEM  (4 * GEMM_STAGE * 4)   // 73728 B (>= 128*132*4 epilogue use)

template <int MODE>
__global__ __launch_bounds__(256, 2) void gemm_nt(const float* __restrict__ A,
                                                  const float* __restrict__ B,
                                                  float* __restrict__ C) {
    extern __shared__ float sm[];
    const int tid  = threadIdx.x;
    const int lane = tid & 31;
    const int wid  = tid >> 5;
    const int g    = lane >> 2;
    const int c    = lane & 3;
    const int wm   = wid & 1;
    const int wn   = wid >> 1;
    const int mbase = blockIdx.y * 128;
    const int nbase = blockIdx.x * 128;

    const int lr = tid >> 3;         // 0..31
    const int lc = (tid & 7) << 2;   // 0..28 step 4

    const float* Ap = A + (size_t)(mbase + lr) * DIMV + lc;
    const float* Bp = B + (size_t)(nbase + lr) * DIMV + lc;

    unsigned sA = smem_u32(&sm[lr * GSTR + lc]);
    unsigned sB = smem_u32(&sm[GEMM_STAGE + lr * GSTR + lc]);
    const unsigned stageB = 2 * GEMM_STAGE * 4;  // bytes per stage

    float acc[4][4][4];
#pragma unroll
    for (int i = 0; i < 4; i++)
#pragma unroll
        for (int j = 0; j < 4; j++)
#pragma unroll
            for (int e = 0; e < 4; e++) acc[i][j][e] = 0.f;

#pragma unroll
    for (int r = 0; r < 4; r++) {
        CP_ASYNC16(sA + r * 32 * GSTR * 4, Ap + (size_t)r * 32 * DIMV);
        CP_ASYNC16(sB + r * 32 * GSTR * 4, Bp + (size_t)r * 32 * DIMV);
    }
    CP_COMMIT();

    const int NT = DIMV / 32;
    for (int t = 0; t < NT; t++) {
        if (t + 1 < NT) {
            const float* An = Ap + (t + 1) * 32;
            const float* Bn = Bp + (t + 1) * 32;
            const unsigned so = ((t + 1) & 1) * stageB;
#pragma unroll
            for (int r = 0; r < 4; r++) {
                CP_ASYNC16(sA + so + r * 32 * GSTR * 4, An + (size_t)r * 32 * DIMV);
                CP_ASYNC16(sB + so + r * 32 * GSTR * 4, Bn + (size_t)r * 32 * DIMV);
            }
            CP_COMMIT();
            CP_WAIT1();
        } else {
            CP_WAIT0();
        }
        __syncthreads();

        const float* As = sm + (t & 1) * 2 * GEMM_STAGE;
        const float* Bs = As + GEMM_STAGE;

#pragma unroll
        for (int kk = 0; kk < 4; kk++) {
            const int k0 = kk << 3;
            float a[4][4];
#pragma unroll
            for (int mf = 0; mf < 4; mf++) {
                const int row = wm * 64 + mf * 16;
                a[mf][0] = As[(row + g) * GSTR + k0 + c];
                a[mf][1] = As[(row + g + 8) * GSTR + k0 + c];
                a[mf][2] = As[(row + g) * GSTR + k0 + c + 4];
                a[mf][3] = As[(row + g + 8) * GSTR + k0 + c + 4];
            }
#pragma unroll
            for (int nf = 0; nf < 4; nf++) {
                const int col = wn * 32 + nf * 8;
                float b2[2];
                b2[0] = Bs[(col + g) * GSTR + k0 + c];
                b2[1] = Bs[(col + g) * GSTR + k0 + c + 4];
#pragma unroll
                for (int mf = 0; mf < 4; mf++) mma8(acc[mf][nf], a[mf], b2);
            }
        }
        __syncthreads();
    }

    if (MODE == 1 || MODE == 2) {
        // RoPE epilogue: acc -> smem (all warps past the final barrier; the
        // pipeline buffer is dead), then transform + write.
        float* Cs = sm;  // 128 x 132 = 67584 floats*4 <= 73728 B
#pragma unroll
        for (int mf = 0; mf < 4; mf++) {
            const int row = wm * 64 + mf * 16 + g;
#pragma unroll
            for (int nf = 0; nf < 4; nf++) {
                const int col = wn * 32 + nf * 8 + 2 * c;
                *(float2*)&Cs[row * 132 + col] =
                    make_float2(acc[mf][nf][0], acc[mf][nf][1]);
                *(float2*)&Cs[(row + 8) * 132 + col] =
                    make_float2(acc[mf][nf][2], acc[mf][nf][3]);
            }
        }
        __syncthreads();
        const float SC = (MODE == 1) ? 0.08838834764831845f : 1.0f;
        for (int p = tid; p < 128 * 32; p += 256) {
            const int r  = p >> 5;
            const int f4 = (p & 31) << 2;
            const int m  = mbase + r;
            const int s  = m & (SEQ - 1);
            const float* crow = &Cs[r * 132];
            float v[4];
            if (f4 < 64) {
#pragma unroll
                for (int e = 0; e < 4; e++) {
                    const int j = f4 + e;
                    const float cs = g_tcos[(s << 6) + j];
                    const float sn = g_tsin[(s << 6) + j];
                    v[e] = tf32r((crow[j] * cs - crow[2 * j + 1] * sn) * SC);
                }
            } else {
#pragma unroll
                for (int e = 0; e < 4; e++) {
                    const int j = f4 - 64 + e;
                    const float cs = g_tcos[(s << 6) + j];
                    const float sn = g_tsin[(s << 6) + j];
                    v[e] = tf32r((crow[j + 64] * cs + crow[2 * j] * sn) * SC);
                }
            }
            *(float4*)&C[(size_t)m * DIMV + nbase + f4] =
                make_float4(v[0], v[1], v[2], v[3]);
        }
    } else {
#pragma unroll
        for (int mf = 0; mf < 4; mf++) {
            const int row = mbase + wm * 64 + mf * 16 + g;
#pragma unroll
            for (int nf = 0; nf < 4; nf++) {
                const int col = nbase + wn * 32 + nf * 8 + 2 * c;
                float o0 = acc[mf][nf][0], o1 = acc[mf][nf][1];
                float o2 = acc[mf][nf][2], o3 = acc[mf][nf][3];
                if (MODE == 3) {
                    o0 = tf32r(o0); o1 = tf32r(o1);
                    o2 = tf32r(o2); o3 = tf32r(o3);
                }
                *(float2*)&C[(size_t)row * DIMV + col] = make_float2(o0, o1);
                *(float2*)&C[(size_t)(row + 8) * DIMV + col] = make_float2(o2, o3);
            }
        }
    }
}

// ---------------------------------------------------------------------------
// RoPE tables. 64 distinct inv_freq via tiny FP64 kernel; float table build.
// ---------------------------------------------------------------------------
__global__ void invf_kernel() {
    int j = threadIdx.x;
    if (j < 64)
        g_invf[j] = (float)exp(-(double)j * 0.14391156831212787);  // ln(1e4)/64
}

__global__ void rope_tables() {
    int idx = blockIdx.x * blockDim.x + threadIdx.x;
    if (idx >= SEQ * 64) return;
    int s = idx >> 6, j = idx & 63;
    float a = (float)s * g_invf[j];
    float sn, cs;
    sincosf(a, &sn, &cs);
    g_tcos[idx] = cs;
    g_tsin[idx] = sn;
}

// ---------------------------------------------------------------------------
// Causal flash attention. One block = 128 query rows of one (b,h).
// 8 warps x 16 q-rows, Bkv=64, 256 threads, cp.async pipeline:
//   Q staged once; K double-buffered (prefetched one full iteration ahead);
//   V single-buffered, issued at iteration top, awaited only before PV
//   (hidden behind S-phase + softmax). P is per-warp private (no barriers).
// All inputs pre-tf32-rounded by the GEMM epilogues -> zero cvt here.
// Strides mod 32 keep all frag loads bank-conflict-free:
//   Q/K 132 (->4g+c), V 136 (->8c+g), P 68 (->4g+c).
// Smem: Q 67584 + 2x K 33792 + V 34816 + P 34816 = 204800 B (1 CTA/SM).
// ---------------------------------------------------------------------------
#define QSTR 132
#define KSTR 132
#define VSTR 136
#define PSTR 68
#define Q_FLOATS (128 * QSTR)
#define K_FLOATS (64 * KSTR)
#define V_FLOATS (64 * VSTR)
#define P_FLOATS (8 * 16 * PSTR)
#define KOFS Q_FLOATS
#define VOFS (KOFS + 2 * K_FLOATS)
#define POFS (VOFS + V_FLOATS)
#define FLASH_SMEM ((POFS + P_FLOATS) * 4)   // 204800

__global__ __launch_bounds__(256) void flash_kernel() {
    extern __shared__ float sm[];
    float* Qs = sm;
    float* Vs = sm + VOFS;

    const int tid  = threadIdx.x;
    const int lane = tid & 31;
    const int w    = tid >> 5;
    const int g    = lane >> 2;
    const int c    = lane & 3;

    const int qt = (int)gridDim.x - 1 - (int)blockIdx.x;  // heavy tiles first
    const int h  = blockIdx.y;
    const int b  = blockIdx.z;
    const int q0 = qt * 128;
    const size_t brow = (size_t)b * SEQ;
    const int hcol = h * HDIM;
    const int nkt = 2 * qt + 2;

    // Prologue: Q (once) + K tile 0
    for (int idx = tid; idx < 128 * 32; idx += 256) {
        int r = idx >> 5, d4 = (idx & 31) << 2;
        CP_ASYNC16(smem_u32(&Qs[r * QSTR + d4]),
                   &g_qr[(brow + q0 + r) * DIMV + hcol + d4]);
    }
    for (int idx = tid; idx < 64 * 32; idx += 256) {
        int r = idx >> 5, d4 = (idx & 31) << 2;
        CP_ASYNC16(smem_u32(&sm[KOFS + r * KSTR + d4]),
                   &g_kr[(brow + r) * DIMV + hcol + d4]);
    }
    CP_COMMIT();

    float O[16][4];
#pragma unroll
    for (int nf = 0; nf < 16; nf++)
#pragma unroll
        for (int e = 0; e < 4; e++) O[nf][e] = 0.f;
    float m0 = -1e30f, m1 = -1e30f, l0 = 0.f, l1 = 0.f;
    float* Pw = sm + POFS + w * 16 * PSTR;

    for (int kt = 0; kt < nkt; kt++) {
        CP_WAIT0();          // K(kt) landed (and prior V/Q)
        __syncthreads();     // publish K; all warps done with old V

        const float* Ks = sm + KOFS + (kt & 1) * K_FLOATS;
        const bool pre = (kt + 1 < nkt);

        // Issue V(kt) — awaited before PV, hidden behind S + softmax
        for (int idx = tid; idx < 64 * 32; idx += 256) {
            int r = idx >> 5, d4 = (idx & 31) << 2;
            CP_ASYNC16(smem_u32(&Vs[r * VSTR + d4]),
                       &g_v[(brow + (size_t)kt * 64 + r) * DIMV + hcol + d4]);
        }
        CP_COMMIT();
        // Prefetch K(kt+1) — awaited at next iteration top
        if (pre) {
            float* Kn = sm + KOFS + ((kt + 1) & 1) * K_FLOATS;
            for (int idx = tid; idx < 64 * 32; idx += 256) {
                int r = idx >> 5, d4 = (idx & 31) << 2;
                CP_ASYNC16(smem_u32(&Kn[r * KSTR + d4]),
                           &g_kr[(brow + (size_t)(kt + 1) * 64 + r) * DIMV + hcol + d4]);
            }
            CP_COMMIT();
        }

        // ---- S = Q K^T (16 x 64 per warp) ----
        float sacc[8][4];
#pragma unroll
        for (int nf = 0; nf < 8; nf++)
#pragma unroll
            for (int e = 0; e < 4; e++) sacc[nf][e] = 0.f;

        const int arow = (w * 16 + g) * QSTR;
#pragma unroll
        for (int k0 = 0; k0 < 128; k0 += 8) {
            float a[4];
            a[0] = Qs[arow + k0 + c];
            a[1] = Qs[arow + 8 * QSTR + k0 + c];
            a[2] = Qs[arow + k0 + c + 4];
            a[3] = Qs[arow + 8 * QSTR + k0 + c + 4];
#pragma unroll
            for (int nf = 0; nf < 8; nf++) {
                float b2[2];
                b2[0] = Ks[(nf * 8 + g) * KSTR + k0 + c];
                b2[1] = Ks[(nf * 8 + g) * KSTR + k0 + c + 4];
                mma8(sacc[nf], a, b2);
            }
        }

        // Causal mask (only last two kv tiles can cross the diagonal)
        if (kt + 2 >= nkt) {
            const int gr = q0 + w * 16 + g;
            const int gc = kt * 64;
#pragma unroll
            for (int nf = 0; nf < 8; nf++) {
                const int col0 = gc + nf * 8 + 2 * c;
                if (col0     > gr)     sacc[nf][0] = -1e30f;
                if (col0 + 1 > gr)     sacc[nf][1] = -1e30f;
                if (col0     > gr + 8) sacc[nf][2] = -1e30f;
                if (col0 + 1 > gr + 8) sacc[nf][3] = -1e30f;
            }
        }

        // Row max (in-thread + quad shuffle)
        float rm0 = -1e30f, rm1 = -1e30f;
#pragma unroll
        for (int nf = 0; nf < 8; nf++) {
            rm0 = fmaxf(rm0, fmaxf(sacc[nf][0], sacc[nf][1]));
            rm1 = fmaxf(rm1, fmaxf(sacc[nf][2], sacc[nf][3]));
        }
        rm0 = fmaxf(rm0, __shfl_xor_sync(0xffffffffu, rm0, 1));
        rm0 = fmaxf(rm0, __shfl_xor_sync(0xffffffffu, rm0, 2));
        rm1 = fmaxf(rm1, __shfl_xor_sync(0xffffffffu, rm1, 1));
        rm1 = fmaxf(rm1, __shfl_xor_sync(0xffffffffu, rm1, 2));

        const float mn0 = fmaxf(m0, rm0), mn1 = fmaxf(m1, rm1);
        const float al0 = expf(m0 - mn0), al1 = expf(m1 - mn1);

        float ps0 = 0.f, ps1 = 0.f;
#pragma unroll
        for (int nf = 0; nf < 8; nf++) {       // exp in place
            sacc[nf][0] = expf(sacc[nf][0] - mn0);
            sacc[nf][1] = expf(sacc[nf][1] - mn0);
            sacc[nf][2] = expf(sacc[nf][2] - mn1);
            sacc[nf][3] = expf(sacc[nf][3] - mn1);
            ps0 += sacc[nf][0] + sacc[nf][1];
            ps1 += sacc[nf][2] + sacc[nf][3];
        }
        ps0 += __shfl_xor_sync(0xffffffffu, ps0, 1);
        ps0 += __shfl_xor_sync(0xffffffffu, ps0, 2);
        ps1 += __shfl_xor_sync(0xffffffffu, ps1, 1);
        ps1 += __shfl_xor_sync(0xffffffffu, ps1, 2);
        l0 = l0 * al0 + ps0;
        l1 = l1 * al1 + ps1;
        m0 = mn0; m1 = mn1;

#pragma unroll
        for (int nf = 0; nf < 16; nf++) {
            O[nf][0] *= al0; O[nf][1] *= al0;
            O[nf][2] *= al1; O[nf][3] *= al1;
        }

        // Wait for V(kt) (keep K(kt+1) in flight), publish across warps
        if (pre) { CP_WAIT1(); } else { CP_WAIT0(); }
        __syncthreads();

        // P: C-layout -> per-warp smem slice -> A-layout (tf32 for mma)
#pragma unroll
        for (int nf = 0; nf < 8; nf++) {
            const int col = nf * 8 + 2 * c;
            *(float2*)&Pw[g * PSTR + col] =
                make_float2(tf32r(sacc[nf][0]), tf32r(sacc[nf][1]));
            *(float2*)&Pw[(g + 8) * PSTR + col] =
                make_float2(tf32r(sacc[nf][2]), tf32r(sacc[nf][3]));
        }
        __syncwarp();

        // ---- O += P V ----
#pragma unroll
        for (int k0 = 0; k0 < 64; k0 += 8) {
            float a[4];
            a[0] = Pw[g * PSTR + k0 + c];
            a[1] = Pw[(g + 8) * PSTR + k0 + c];
            a[2] = Pw[g * PSTR + k0 + c + 4];
            a[3] = Pw[(g + 8) * PSTR + k0 + c + 4];
#pragma unroll
            for (int nf = 0; nf < 16; nf++) {
                float b2[2];
                b2[0] = Vs[(k0 + c) * VSTR + nf * 8 + g];
                b2[1] = Vs[(k0 + c + 4) * VSTR + nf * 8 + g];
                mma8(O[nf], a, b2);
            }
        }
    }

    // Epilogue: normalize, tf32-round (feeds the Wo GEMM), write [B,S,H*D]
    const float r0 = 1.f / l0, r1 = 1.f / l1;
    const int qrow = q0 + w * 16 + g;
#pragma unroll
    for (int nf = 0; nf < 16; nf++) {
        const int col = hcol + nf * 8 + 2 * c;
        *(float2*)&g_att[(brow + qrow) * DIMV + col] =
            make_float2(tf32r(O[nf][0] * r0), tf32r(O[nf][1] * r0));
        *(float2*)&g_att[(brow + qrow + 8) * DIMV + col] =
            make_float2(tf32r(O[nf][2] * r1), tf32r(O[nf][3] * r1));
    }
}

// ---------------------------------------------------------------------------
// Launch
// ---------------------------------------------------------------------------
extern "C" void kernel_launch(void* const* d_in, const int* in_sizes, int n_in,
                              void* d_out, int out_size) {
    (void)in_sizes; (void)n_in; (void)out_size;
    const float* x  = (const float*)d_in[0];
    const float* Wq = (const float*)d_in[1];
    const float* Wk = (const float*)d_in[2];
    const float* Wv = (const float*)d_in[3];
    const float* Wo = (const float*)d_in[4];
    float* out = (float*)d_out;

    float *pqr, *pkr, *pv, *patt, *pxr, *pwq, *pwk, *pwv, *pwo;
    cudaGetSymbolAddress((void**)&pqr,  g_qr);
    cudaGetSymbolAddress((void**)&pkr,  g_kr);
    cudaGetSymbolAddress((void**)&pv,   g_v);
    cudaGetSymbolAddress((void**)&patt, g_att);
    cudaGetSymbolAddress((void**)&pxr,  g_xr);
    cudaGetSymbolAddress((void**)&pwq,  g_wqr);
    cudaGetSymbolAddress((void**)&pwk,  g_wkr);
    cudaGetSymbolAddress((void**)&pwv,  g_wvr);
    cudaGetSymbolAddress((void**)&pwo,  g_wor);

    cudaFuncSetAttribute(gemm_nt<0>,
                         cudaFuncAttributeMaxDynamicSharedMemorySize, GEMM_SMEM);
    cudaFuncSetAttribute(gemm_nt<1>,
                         cudaFuncAttributeMaxDynamicSharedMemorySize, GEMM_SMEM);
    cudaFuncSetAttribute(gemm_nt<2>,
                         cudaFuncAttributeMaxDynamicSharedMemorySize, GEMM_SMEM);
    cudaFuncSetAttribute(gemm_nt<3>,
                         cudaFuncAttributeMaxDynamicSharedMemorySize, GEMM_SMEM);
    cudaFuncSetAttribute(flash_kernel,
                         cudaFuncAttributeMaxDynamicSharedMemorySize, FLASH_SMEM);

    const int NX4 = GM * DIMV / 4;
    const int NW4 = DIMV * DIMV / 4;
    round_copy<<<(NX4 + 255) / 256, 256>>>(x,  pxr, NX4);
    round_copy<<<(NW4 + 255) / 256, 256>>>(Wq, pwq, NW4);
    round_copy<<<(NW4 + 255) / 256, 256>>>(Wk, pwk, NW4);
    round_copy<<<(NW4 + 255) / 256, 256>>>(Wv, pwv, NW4);
    round_copy<<<(NW4 + 255) / 256, 256>>>(Wo, pwo, NW4);

    invf_kernel<<<1, 64>>>();
    rope_tables<<<(SEQ * 64 + 255) / 256, 256>>>();

    dim3 gg(DIMV / 128, GM / 128);  // (16, 32)
    gemm_nt<1><<<gg, 256, GEMM_SMEM>>>(pxr, pwq, pqr);   // Q: rope+scale+tf32
    gemm_nt<2><<<gg, 256, GEMM_SMEM>>>(pxr, pwk, pkr);   // K: rope+tf32
    gemm_nt<3><<<gg, 256, GEMM_SMEM>>>(pxr, pwv, pv);    // V: tf32
    flash_kernel<<<dim3(SEQ / 128, NHEAD, 2), 256, FLASH_SMEM>>>();
    gemm_nt<0><<<gg, 256, GEMM_SMEM>>>(patt, pwo, out);  // output proj
}

// round 9
// speedup vs baseline: 1.1535x; 1.1535x over previous
#include <cuda_runtime.h>
#include <cstdint>
#include <stdint.h>
#include <math.h>

// ---------------------------------------------------------------------------
// Problem constants: B=2, S=2048, DIM=2048, H=16, HDIM=128
// ---------------------------------------------------------------------------
#define DIMV 2048
#define GM   4096      // B*S rows
#define SEQ  2048
#define NHEAD 16
#define HDIM 128

// Scratch (device globals: allocation-free per harness rules)
__device__ float g_qr [GM * DIMV];          // rope'd + scaled + tf32 q
__device__ float g_kr [GM * DIMV];          // rope'd + tf32 k
__device__ float g_v  [GM * DIMV];          // tf32 v
__device__ float g_att[GM * DIMV];
__device__ float g_xr [GM * DIMV];          // tf32-rounded x
__device__ float g_wqr[DIMV * DIMV];        // tf32-rounded weights
__device__ float g_wkr[DIMV * DIMV];
__device__ float g_wvr[DIMV * DIMV];
__device__ float g_wor[DIMV * DIMV];
__device__ float g_tcos[SEQ * 64];
__device__ float g_tsin[SEQ * 64];
__device__ float g_invf[64];

// ---------------------------------------------------------------------------
// Helpers
// ---------------------------------------------------------------------------
__device__ __forceinline__ float tf32r(float x) {
    unsigned u;
    asm("cvt.rna.tf32.f32 %0, %1;" : "=r"(u) : "f"(x));
    return __uint_as_float(u);
}

__device__ __forceinline__ unsigned smem_u32(const void* p) {
    return (unsigned)__cvta_generic_to_shared(p);
}

#define CP_ASYNC16(dst_u32, src) \
    asm volatile("cp.async.cg.shared.global [%0], [%1], 16;\n" :: "r"(dst_u32), "l"(src))
#define CP_COMMIT() asm volatile("cp.async.commit_group;\n" ::)
#define CP_WAIT1()  asm volatile("cp.async.wait_group 1;\n" ::)
#define CP_WAIT0()  asm volatile("cp.async.wait_group 0;\n" ::)

// mma.sync m16n8k8 tf32 fp32-accum (row.col).
// Frag layout (g=lane>>2, c=lane&3):
//   A: a0=(g,c) a1=(g+8,c) a2=(g,c+4) a3=(g+8,c+4)       [A is m x k]
//   B: b0=(k=c,n=g) b1=(k=c+4,n=g)                        [B is k x n]
//   C: c0=(g,2c) c1=(g,2c+1) c2=(g+8,2c) c3=(g+8,2c+1)
__device__ __forceinline__ void mma8(float* d, const float* a, const float* b) {
    asm volatile(
        "mma.sync.aligned.m16n8k8.row.col.f32.tf32.tf32.f32 "
        "{%0,%1,%2,%3}, {%4,%5,%6,%7}, {%8,%9}, {%0,%1,%2,%3};\n"
        : "+f"(d[0]), "+f"(d[1]), "+f"(d[2]), "+f"(d[3])
        : "r"(__float_as_uint(a[0])), "r"(__float_as_uint(a[1])),
          "r"(__float_as_uint(a[2])), "r"(__float_as_uint(a[3])),
          "r"(__float_as_uint(b[0])), "r"(__float_as_uint(b[1])));
}

// ---------------------------------------------------------------------------
// Fused tf32 pre-round of x + all 4 weights (one launch)
// ---------------------------------------------------------------------------
#define NX4 (GM * DIMV / 4)       // 2097152 float4
#define NW4 (DIMV * DIMV / 4)     // 1048576 float4
#define NALL4 (NX4 + 4 * NW4)     // 6291456

__global__ void round_all(const float* __restrict__ x,
                          const float* __restrict__ wq,
                          const float* __restrict__ wk,
                          const float* __restrict__ wv,
                          const float* __restrict__ wo) {
    long long i = (long long)blockIdx.x * blockDim.x + threadIdx.x;
    if (i >= NALL4) return;
    const float4* src;
    float4* dst;
    long long off;
    if (i < NX4) {
        src = (const float4*)x;  dst = (float4*)g_xr;  off = i;
    } else {
        long long j = i - NX4;
        int r = (int)(j / NW4);
        off = j % NW4;
        if (r == 0)      { src = (const float4*)wq; dst = (float4*)g_wqr; }
        else if (r == 1) { src = (const float4*)wk; dst = (float4*)g_wkr; }
        else if (r == 2) { src = (const float4*)wv; dst = (float4*)g_wvr; }
        else             { src = (const float4*)wo; dst = (float4*)g_wor; }
    }
    float4 v = src[off];
    v.x = tf32r(v.x); v.y = tf32r(v.y); v.z = tf32r(v.z); v.w = tf32r(v.w);
    dst[off] = v;
}

// ---------------------------------------------------------------------------
// RoPE tables. 64 distinct inv_freq via tiny FP64 kernel; float table build.
// ---------------------------------------------------------------------------
__global__ void invf_kernel() {
    int j = threadIdx.x;
    if (j < 64)
        g_invf[j] = (float)exp(-(double)j * 0.14391156831212787);  // ln(1e4)/64
}

__global__ void rope_tables() {
    int idx = blockIdx.x * blockDim.x + threadIdx.x;
    if (idx >= SEQ * 64) return;
    int s = idx >> 6, j = idx & 63;
    float a = (float)s * g_invf[j];
    float sn, cs;
    sincosf(a, &sn, &cs);
    g_tcos[idx] = cs;
    g_tsin[idx] = sn;
}

// ---------------------------------------------------------------------------
// GEMM (NT): C[4096,2048] = A[4096,2048] * W[2048,2048]^T, inputs pre-rounded.
// 128x128x32 tile, 256 threads (2x4 warps), warp tile 64x32, cp.async
// 2-stage pipeline, smem stride 36 (conflict-free frag loads).
// blockIdx.z selects {W, C, mode} -> Q/K/V fused in one launch.
// Epilogue modes: 0 plain fp32; 1 RoPE+scale+tf32 (Q); 2 RoPE+tf32 (K);
// 3 tf32 (V). RoPE bounces the tile through the dead pipeline smem.
// ---------------------------------------------------------------------------
#define GSTR 36
#define GEMM_STAGE (128 * GSTR)
#define GEMM_SMEM  (4 * GEMM_STAGE * 4)   // 73728 B

__global__ __launch_bounds__(256, 2) void gemm_nt(
    const float* __restrict__ A,
    const float* __restrict__ B0, const float* __restrict__ B1,
    const float* __restrict__ B2,
    float* __restrict__ C0, float* __restrict__ C1, float* __restrict__ C2,
    int m0, int m1, int m2) {
    extern __shared__ float sm[];
    const int z = blockIdx.z;
    const float* __restrict__ B = (z == 0) ? B0 : (z == 1) ? B1 : B2;
    float* __restrict__ C       = (z == 0) ? C0 : (z == 1) ? C1 : C2;
    const int mode              = (z == 0) ? m0 : (z == 1) ? m1 : m2;

    const int tid  = threadIdx.x;
    const int lane = tid & 31;
    const int wid  = tid >> 5;
    const int g    = lane >> 2;
    const int c    = lane & 3;
    const int wm   = wid & 1;
    const int wn   = wid >> 1;
    const int mbase = blockIdx.y * 128;
    const int nbase = blockIdx.x * 128;

    const int lr = tid >> 3;         // 0..31
    const int lc = (tid & 7) << 2;   // 0..28 step 4

    const float* Ap = A + (size_t)(mbase + lr) * DIMV + lc;
    const float* Bp = B + (size_t)(nbase + lr) * DIMV + lc;

    unsigned sA = smem_u32(&sm[lr * GSTR + lc]);
    unsigned sB = smem_u32(&sm[GEMM_STAGE + lr * GSTR + lc]);
    const unsigned stageB = 2 * GEMM_STAGE * 4;  // bytes per stage

    float acc[4][4][4];
#pragma unroll
    for (int i = 0; i < 4; i++)
#pragma unroll
        for (int j = 0; j < 4; j++)
#pragma unroll
            for (int e = 0; e < 4; e++) acc[i][j][e] = 0.f;

#pragma unroll
    for (int r = 0; r < 4; r++) {
        CP_ASYNC16(sA + r * 32 * GSTR * 4, Ap + (size_t)r * 32 * DIMV);
        CP_ASYNC16(sB + r * 32 * GSTR * 4, Bp + (size_t)r * 32 * DIMV);
    }
    CP_COMMIT();

    const int NT = DIMV / 32;
    for (int t = 0; t < NT; t++) {
        if (t + 1 < NT) {
            const float* An = Ap + (t + 1) * 32;
            const float* Bn = Bp + (t + 1) * 32;
            const unsigned so = ((t + 1) & 1) * stageB;
#pragma unroll
            for (int r = 0; r < 4; r++) {
                CP_ASYNC16(sA + so + r * 32 * GSTR * 4, An + (size_t)r * 32 * DIMV);
                CP_ASYNC16(sB + so + r * 32 * GSTR * 4, Bn + (size_t)r * 32 * DIMV);
            }
            CP_COMMIT();
            CP_WAIT1();
        } else {
            CP_WAIT0();
        }
        __syncthreads();

        const float* As = sm + (t & 1) * 2 * GEMM_STAGE;
        const float* Bs = As + GEMM_STAGE;

#pragma unroll
        for (int kk = 0; kk < 4; kk++) {
            const int k0 = kk << 3;
            float a[4][4];
#pragma unroll
            for (int mf = 0; mf < 4; mf++) {
                const int row = wm * 64 + mf * 16;
                a[mf][0] = As[(row + g) * GSTR + k0 + c];
                a[mf][1] = As[(row + g + 8) * GSTR + k0 + c];
                a[mf][2] = As[(row + g) * GSTR + k0 + c + 4];
                a[mf][3] = As[(row + g + 8) * GSTR + k0 + c + 4];
            }
#pragma unroll
            for (int nf = 0; nf < 4; nf++) {
                const int col = wn * 32 + nf * 8;
                float b2[2];
                b2[0] = Bs[(col + g) * GSTR + k0 + c];
                b2[1] = Bs[(col + g) * GSTR + k0 + c + 4];
#pragma unroll
                for (int mf = 0; mf < 4; mf++) mma8(acc[mf][nf], a[mf], b2);
            }
        }
        __syncthreads();
    }

    if (mode == 1 || mode == 2) {
        // RoPE epilogue: acc -> smem (pipeline bufs dead) -> transform -> gmem
        float* Cs = sm;  // 128 x 132 floats = 67584 B <= 73728
#pragma unroll
        for (int mf = 0; mf < 4; mf++) {
            const int row = wm * 64 + mf * 16 + g;
#pragma unroll
            for (int nf = 0; nf < 4; nf++) {
                const int col = wn * 32 + nf * 8 + 2 * c;
                *(float2*)&Cs[row * 132 + col] =
                    make_float2(acc[mf][nf][0], acc[mf][nf][1]);
                *(float2*)&Cs[(row + 8) * 132 + col] =
                    make_float2(acc[mf][nf][2], acc[mf][nf][3]);
            }
        }
        __syncthreads();
        const float SC = (mode == 1) ? 0.08838834764831845f : 1.0f;
        for (int p = tid; p < 128 * 32; p += 256) {
            const int r  = p >> 5;
            const int f4 = (p & 31) << 2;
            const int m  = mbase + r;
            const int s  = m & (SEQ - 1);
            const float* crow = &Cs[r * 132];
            float v[4];
            if (f4 < 64) {
#pragma unroll
                for (int e = 0; e < 4; e++) {
                    const int j = f4 + e;
                    const float cs = g_tcos[(s << 6) + j];
                    const float sn = g_tsin[(s << 6) + j];
                    v[e] = tf32r((crow[j] * cs - crow[2 * j + 1] * sn) * SC);
                }
            } else {
#pragma unroll
                for (int e = 0; e < 4; e++) {
                    const int j = f4 - 64 + e;
                    const float cs = g_tcos[(s << 6) + j];
                    const float sn = g_tsin[(s << 6) + j];
                    v[e] = tf32r((crow[j + 64] * cs + crow[2 * j] * sn) * SC);
                }
            }
            *(float4*)&C[(size_t)m * DIMV + nbase + f4] =
                make_float4(v[0], v[1], v[2], v[3]);
        }
    } else {
#pragma unroll
        for (int mf = 0; mf < 4; mf++) {
            const int row = mbase + wm * 64 + mf * 16 + g;
#pragma unroll
            for (int nf = 0; nf < 4; nf++) {
                const int col = nbase + wn * 32 + nf * 8 + 2 * c;
                float o0 = acc[mf][nf][0], o1 = acc[mf][nf][1];
                float o2 = acc[mf][nf][2], o3 = acc[mf][nf][3];
                if (mode == 3) {
                    o0 = tf32r(o0); o1 = tf32r(o1);
                    o2 = tf32r(o2); o3 = tf32r(o3);
                }
                *(float2*)&C[(size_t)row * DIMV + col] = make_float2(o0, o1);
                *(float2*)&C[(size_t)(row + 8) * DIMV + col] = make_float2(o2, o3);
            }
        }
    }
}

// ---------------------------------------------------------------------------
// Causal flash attention. One block = 64 query rows of one (b,h); 4 warps.
// Bkv=64. cp.async staging with split commit groups: K awaited before the
// S phase, V awaited only before PV (hidden behind S + softmax). P aliases
// the K region (dead after S; barrier-separated). __expf softmax.
// Smem 102400 B -> 2 CTAs/SM. Strides mod 32 keep frag loads conflict-free.
// ---------------------------------------------------------------------------
#define QSTR 132
#define KSTR 132
#define VSTR 136
#define PSTR 68
#define KOFS (64 * QSTR)
#define VOFS (KOFS + 64 * KSTR)
#define FLASH_SMEM ((VOFS + 64 * VSTR) * 4)   // 102400

__global__ __launch_bounds__(128) void flash_kernel() {
    extern __shared__ float sm[];
    float* Qs = sm;
    float* Ks = sm + KOFS;     // re-used as P after the S phase
    float* Vs = sm + VOFS;

    const int tid  = threadIdx.x;
    const int lane = tid & 31;
    const int w    = tid >> 5;
    const int g    = lane >> 2;
    const int c    = lane & 3;

    const int qt = (int)gridDim.x - 1 - (int)blockIdx.x;  // heavy tiles first
    const int h  = blockIdx.y;
    const int b  = blockIdx.z;
    const int q0 = qt * 64;
    const size_t brow = (size_t)b * SEQ;
    const int hcol = h * HDIM;

    // Stage Q once (pre-rounded, scale folded in)
    for (int idx = tid; idx < 64 * 32; idx += 128) {
        int r = idx >> 5, d4 = (idx & 31) << 2;
        CP_ASYNC16(smem_u32(&Qs[r * QSTR + d4]),
                   &g_qr[(brow + q0 + r) * DIMV + hcol + d4]);
    }
    CP_COMMIT();

    float O[16][4];
#pragma unroll
    for (int nf = 0; nf < 16; nf++)
#pragma unroll
        for (int e = 0; e < 4; e++) O[nf][e] = 0.f;
    float m0 = -1e30f, m1 = -1e30f, l0 = 0.f, l1 = 0.f;
    float* Pw = Ks + w * 16 * PSTR;   // alias into K region

    for (int kt = 0; kt <= qt; kt++) {
        __syncthreads();   // prior iter's P/V reads done before restaging
        // K group, then V group (separate commits)
        for (int idx = tid; idx < 64 * 32; idx += 128) {
            int r = idx >> 5, d4 = (idx & 31) << 2;
            CP_ASYNC16(smem_u32(&Ks[r * KSTR + d4]),
                       &g_kr[(brow + (size_t)kt * 64 + r) * DIMV + hcol + d4]);
        }
        CP_COMMIT();
        for (int idx = tid; idx < 64 * 32; idx += 128) {
            int r = idx >> 5, d4 = (idx & 31) << 2;
            CP_ASYNC16(smem_u32(&Vs[r * VSTR + d4]),
                       &g_v[(brow + (size_t)kt * 64 + r) * DIMV + hcol + d4]);
        }
        CP_COMMIT();
        CP_WAIT1();        // K (and Q on first iter) landed; V in flight
        __syncthreads();

        // ---- S = Q K^T (16 x 64 per warp) ----
        float sacc[8][4];
#pragma unroll
        for (int nf = 0; nf < 8; nf++)
#pragma unroll
            for (int e = 0; e < 4; e++) sacc[nf][e] = 0.f;

        const int arow = (w * 16 + g) * QSTR;
#pragma unroll
        for (int k0 = 0; k0 < 128; k0 += 8) {
            float a[4];
            a[0] = Qs[arow + k0 + c];
            a[1] = Qs[arow + 8 * QSTR + k0 + c];
            a[2] = Qs[arow + k0 + c + 4];
            a[3] = Qs[arow + 8 * QSTR + k0 + c + 4];
#pragma unroll
            for (int nf = 0; nf < 8; nf++) {
                float b2[2];
                b2[0] = Ks[(nf * 8 + g) * KSTR + k0 + c];
                b2[1] = Ks[(nf * 8 + g) * KSTR + k0 + c + 4];
                mma8(sacc[nf], a, b2);
            }
        }

        // Causal mask on the diagonal tile (local coords: q0 == kt*64 there)
        if (kt == qt) {
            const int r0 = w * 16 + g;
#pragma unroll
            for (int nf = 0; nf < 8; nf++) {
                const int col0 = nf * 8 + 2 * c;
                if (col0     > r0)     sacc[nf][0] = -1e30f;
                if (col0 + 1 > r0)     sacc[nf][1] = -1e30f;
                if (col0     > r0 + 8) sacc[nf][2] = -1e30f;
                if (col0 + 1 > r0 + 8) sacc[nf][3] = -1e30f;
            }
        }

        // Row max (in-thread + quad shuffle)
        float rm0 = -1e30f, rm1 = -1e30f;
#pragma unroll
        for (int nf = 0; nf < 8; nf++) {
            rm0 = fmaxf(rm0, fmaxf(sacc[nf][0], sacc[nf][1]));
            rm1 = fmaxf(rm1, fmaxf(sacc[nf][2], sacc[nf][3]));
        }
        rm0 = fmaxf(rm0, __shfl_xor_sync(0xffffffffu, rm0, 1));
        rm0 = fmaxf(rm0, __shfl_xor_sync(0xffffffffu, rm0, 2));
        rm1 = fmaxf(rm1, __shfl_xor_sync(0xffffffffu, rm1, 1));
        rm1 = fmaxf(rm1, __shfl_xor_sync(0xffffffffu, rm1, 2));

        const float mn0 = fmaxf(m0, rm0), mn1 = fmaxf(m1, rm1);
        const float al0 = __expf(m0 - mn0), al1 = __expf(m1 - mn1);

        float ps0 = 0.f, ps1 = 0.f;
#pragma unroll
        for (int nf = 0; nf < 8; nf++) {   // exp in place (MUFU fast path)
            sacc[nf][0] = __expf(sacc[nf][0] - mn0);
            sacc[nf][1] = __expf(sacc[nf][1] - mn0);
            sacc[nf][2] = __expf(sacc[nf][2] - mn1);
            sacc[nf][3] = __expf(sacc[nf][3] - mn1);
            ps0 += sacc[nf][0] + sacc[nf][1];
            ps1 += sacc[nf][2] + sacc[nf][3];
        }
        ps0 += __shfl_xor_sync(0xffffffffu, ps0, 1);
        ps0 += __shfl_xor_sync(0xffffffffu, ps0, 2);
        ps1 += __shfl_xor_sync(0xffffffffu, ps1, 1);
        ps1 += __shfl_xor_sync(0xffffffffu, ps1, 2);
        l0 = l0 * al0 + ps0;
        l1 = l1 * al1 + ps1;
        m0 = mn0; m1 = mn1;

#pragma unroll
        for (int nf = 0; nf < 16; nf++) {
            O[nf][0] *= al0; O[nf][1] *= al0;
            O[nf][2] *= al1; O[nf][3] *= al1;
        }

        CP_WAIT0();        // V landed
        __syncthreads();   // all warps done READING K before P overwrites

        // P: C-layout -> per-warp smem slice (K region) -> A-layout
#pragma unroll
        for (int nf = 0; nf < 8; nf++) {
            const int col = nf * 8 + 2 * c;
            *(float2*)&Pw[g * PSTR + col] =
                make_float2(tf32r(sacc[nf][0]), tf32r(sacc[nf][1]));
            *(float2*)&Pw[(g + 8) * PSTR + col] =
                make_float2(tf32r(sacc[nf][2]), tf32r(sacc[nf][3]));
        }
        __syncwarp();

        // ---- O += P V ----
#pragma unroll
        for (int k0 = 0; k0 < 64; k0 += 8) {
            float a[4];
            a[0] = Pw[g * PSTR + k0 + c];
            a[1] = Pw[(g + 8) * PSTR + k0 + c];
            a[2] = Pw[g * PSTR + k0 + c + 4];
            a[3] = Pw[(g + 8) * PSTR + k0 + c + 4];
#pragma unroll
            for (int nf = 0; nf < 16; nf++) {
                float b2[2];
                b2[0] = Vs[(k0 + c) * VSTR + nf * 8 + g];
                b2[1] = Vs[(k0 + c + 4) * VSTR + nf * 8 + g];
                mma8(O[nf], a, b2);
            }
        }
    }

    // Epilogue: normalize, tf32-round (feeds the Wo GEMM), write [B,S,H*D]
    const float r0 = 1.f / l0, r1 = 1.f / l1;
    const int qrow = q0 + w * 16 + g;
#pragma unroll
    for (int nf = 0; nf < 16; nf++) {
        const int col = hcol + nf * 8 + 2 * c;
        *(float2*)&g_att[(brow + qrow) * DIMV + col] =
            make_float2(tf32r(O[nf][0] * r0), tf32r(O[nf][1] * r0));
        *(float2*)&g_att[(brow + qrow + 8) * DIMV + col] =
            make_float2(tf32r(O[nf][2] * r1), tf32r(O[nf][3] * r1));
    }
}

// ---------------------------------------------------------------------------
// Launch. 6 launches total; ncu (-s 5 -c 1) captures the Wo GEMM.
// ---------------------------------------------------------------------------
extern "C" void kernel_launch(void* const* d_in, const int* in_sizes, int n_in,
                              void* d_out, int out_size) {
    (void)in_sizes; (void)n_in; (void)out_size;
    const float* x  = (const float*)d_in[0];
    const float* Wq = (const float*)d_in[1];
    const float* Wk = (const float*)d_in[2];
    const float* Wv = (const float*)d_in[3];
    const float* Wo = (const float*)d_in[4];
    float* out = (float*)d_out;

    float *pqr, *pkr, *pv, *patt, *pxr, *pwq, *pwk, *pwv, *pwo;
    cudaGetSymbolAddress((void**)&pqr,  g_qr);
    cudaGetSymbolAddress((void**)&pkr,  g_kr);
    cudaGetSymbolAddress((void**)&pv,   g_v);
    cudaGetSymbolAddress((void**)&patt, g_att);
    cudaGetSymbolAddress((void**)&pxr,  g_xr);
    cudaGetSymbolAddress((void**)&pwq,  g_wqr);
    cudaGetSymbolAddress((void**)&pwk,  g_wkr);
    cudaGetSymbolAddress((void**)&pwv,  g_wvr);
    cudaGetSymbolAddress((void**)&pwo,  g_wor);

    cudaFuncSetAttribute(gemm_nt,
                         cudaFuncAttributeMaxDynamicSharedMemorySize, GEMM_SMEM);
    cudaFuncSetAttribute(flash_kernel,
                         cudaFuncAttributeMaxDynamicSharedMemorySize, FLASH_SMEM);

    round_all<<<(NALL4 + 255) / 256, 256>>>(x, Wq, Wk, Wv, Wo);
    invf_kernel<<<1, 64>>>();
    rope_tables<<<(SEQ * 64 + 255) / 256, 256>>>();

    dim3 gq(DIMV / 128, GM / 128, 3);   // Q,K,V fused
    gemm_nt<<<gq, 256, GEMM_SMEM>>>(pxr, pwq, pwk, pwv, pqr, pkr, pv, 1, 2, 3);
    flash_kernel<<<dim3(SEQ / 64, NHEAD, 2), 128, FLASH_SMEM>>>();
    dim3 go(DIMV / 128, GM / 128, 1);   // output projection (ncu capture slot)
    gemm_nt<<<go, 256, GEMM_SMEM>>>(patt, pwo, pwo, pwo, out, out, out, 0, 0, 0);
}

// round 10
// speedup vs baseline: 1.2762x; 1.1064x over previous
#include <cuda_runtime.h>
#include <cstdint>
#include <stdint.h>
#include <math.h>

// ---------------------------------------------------------------------------
// Problem constants: B=2, S=2048, DIM=2048, H=16, HDIM=128
// ---------------------------------------------------------------------------
#define DIMV 2048
#define GM   4096      // B*S rows
#define SEQ  2048
#define NHEAD 16
#define HDIM 128

// Scratch (device globals: allocation-free per harness rules)
__device__ float g_qr [GM * DIMV];          // rope'd + scaled + tf32 q
__device__ float g_kr [GM * DIMV];          // rope'd + tf32 k
__device__ float g_v  [GM * DIMV];          // tf32 v
__device__ float g_att[GM * DIMV];
__device__ float g_xr [GM * DIMV];          // tf32-rounded x
__device__ float g_wqr[DIMV * DIMV];        // tf32-rounded weights
__device__ float g_wkr[DIMV * DIMV];
__device__ float g_wvr[DIMV * DIMV];
__device__ float g_wor[DIMV * DIMV];
__device__ float g_tcos[SEQ * 64];
__device__ float g_tsin[SEQ * 64];
__device__ float g_invf[64];

// ---------------------------------------------------------------------------
// Helpers
// ---------------------------------------------------------------------------
__device__ __forceinline__ float tf32r(float x) {
    unsigned u;
    asm("cvt.rna.tf32.f32 %0, %1;" : "=r"(u) : "f"(x));
    return __uint_as_float(u);
}

__device__ __forceinline__ unsigned smem_u32(const void* p) {
    return (unsigned)__cvta_generic_to_shared(p);
}

#define CP_ASYNC16(dst_u32, src) \
    asm volatile("cp.async.cg.shared.global [%0], [%1], 16;\n" :: "r"(dst_u32), "l"(src))
#define CP_COMMIT() asm volatile("cp.async.commit_group;\n" ::)
#define CP_WAIT1()  asm volatile("cp.async.wait_group 1;\n" ::)
#define CP_WAIT0()  asm volatile("cp.async.wait_group 0;\n" ::)

// ldmatrix x4: four 8x8 b16 matrices == four 8x4 f32 blocks.
// Thread t of matrix m gets f32 element (row t%8 ... addressed by lanes) ->
// result reg i = matrix i, thread t holds (t/4, t%4) f32 of that block.
#define LDSM_X4(r0, r1, r2, r3, addr) \
    asm volatile("ldmatrix.sync.aligned.m8n8.x4.shared.b16 {%0,%1,%2,%3}, [%4];" \
                 : "=r"(r0), "=r"(r1), "=r"(r2), "=r"(r3) : "r"(addr))

// mma.sync m16n8k8 tf32 fp32-accum (row.col), operands as raw b32.
// A: a0=(g,c) a1=(g+8,c) a2=(g,c+4) a3=(g+8,c+4)   [g=lane>>2, c=lane&3]
// B: b0=(k=c,n=g) b1=(k=c+4,n=g)
// C: c0=(g,2c) c1=(g,2c+1) c2=(g+8,2c) c3=(g+8,2c+1)
__device__ __forceinline__ void mma8u(float* d, const uint32_t* a,
                                      uint32_t b0, uint32_t b1) {
    asm volatile(
        "mma.sync.aligned.m16n8k8.row.col.f32.tf32.tf32.f32 "
        "{%0,%1,%2,%3}, {%4,%5,%6,%7}, {%8,%9}, {%0,%1,%2,%3};\n"
        : "+f"(d[0]), "+f"(d[1]), "+f"(d[2]), "+f"(d[3])
        : "r"(a[0]), "r"(a[1]), "r"(a[2]), "r"(a[3]), "r"(b0), "r"(b1));
}

// ---------------------------------------------------------------------------
// Fused tf32 pre-round of x + all 4 weights (one launch, MLP=4)
// ---------------------------------------------------------------------------
#define NX4 (GM * DIMV / 4)       // 2097152 float4
#define NW4 (DIMV * DIMV / 4)     // 1048576 float4
#define NALL4 (NX4 + 4 * NW4)     // 6291456 (multiple of 1024)

__global__ void round_all(const float* __restrict__ x,
                          const float* __restrict__ wq,
                          const float* __restrict__ wk,
                          const float* __restrict__ wv,
                          const float* __restrict__ wo) {
    long long base = (long long)blockIdx.x * (blockDim.x * 4) + threadIdx.x;
#pragma unroll
    for (int u = 0; u < 4; u++) {
        long long i = base + (long long)u * blockDim.x;
        if (i >= NALL4) return;
        const float4* src;
        float4* dst;
        long long off;
        if (i < NX4) {
            src = (const float4*)x;  dst = (float4*)g_xr;  off = i;
        } else {
            long long j = i - NX4;
            int r = (int)(j / NW4);
            off = j % NW4;
            if (r == 0)      { src = (const float4*)wq; dst = (float4*)g_wqr; }
            else if (r == 1) { src = (const float4*)wk; dst = (float4*)g_wkr; }
            else if (r == 2) { src = (const float4*)wv; dst = (float4*)g_wvr; }
            else             { src = (const float4*)wo; dst = (float4*)g_wor; }
        }
        float4 v = src[off];
        v.x = tf32r(v.x); v.y = tf32r(v.y); v.z = tf32r(v.z); v.w = tf32r(v.w);
        dst[off] = v;
    }
}

// ---------------------------------------------------------------------------
// RoPE tables. 64 distinct inv_freq via tiny FP64 kernel; float table build.
// ---------------------------------------------------------------------------
__global__ void invf_kernel() {
    int j = threadIdx.x;
    if (j < 64)
        g_invf[j] = (float)exp(-(double)j * 0.14391156831212787);  // ln(1e4)/64
}

__global__ void rope_tables() {
    int idx = blockIdx.x * blockDim.x + threadIdx.x;
    if (idx >= SEQ * 64) return;
    int s = idx >> 6, j = idx & 63;
    float a = (float)s * g_invf[j];
    float sn, cs;
    sincosf(a, &sn, &cs);
    g_tcos[idx] = cs;
    g_tsin[idx] = sn;
}

// ---------------------------------------------------------------------------
// GEMM (NT): C[4096,2048] = A[4096,2048] * W[2048,2048]^T, inputs pre-rounded.
// 128x128x32 tile, 256 threads (2x4 warps), warp tile 64x32.
// 3-stage cp.async pipeline, ONE __syncthreads per k-tile (WAR distance 2).
// All fragment loads via ldmatrix (stride 36 == 4 mod 32: conflict-free).
// blockIdx.z selects {W, C, mode}: Q/K/V fused in one launch.
// Epilogue modes: 0 plain fp32; 1 RoPE+scale+tf32 (Q); 2 RoPE+tf32 (K);
// 3 tf32 (V). RoPE bounces the tile through the dead pipeline smem.
// ---------------------------------------------------------------------------
#define GSTR 36
#define STAGE_F (2 * 128 * GSTR)          // floats per stage (A + B)
#define GEMM_SMEM (3 * STAGE_F * 4)       // 110592 B -> 2 CTAs/SM

__global__ __launch_bounds__(256, 2) void gemm_nt(
    const float* __restrict__ A,
    const float* __restrict__ B0, const float* __restrict__ B1,
    const float* __restrict__ B2,
    float* __restrict__ C0, float* __restrict__ C1, float* __restrict__ C2,
    int m0, int m1, int m2) {
    extern __shared__ float sm[];
    const int z = blockIdx.z;
    const float* __restrict__ B = (z == 0) ? B0 : (z == 1) ? B1 : B2;
    float* __restrict__ C       = (z == 0) ? C0 : (z == 1) ? C1 : C2;
    const int mode              = (z == 0) ? m0 : (z == 1) ? m1 : m2;

    const int tid  = threadIdx.x;
    const int lane = tid & 31;
    const int wid  = tid >> 5;
    const int g    = lane >> 2;
    const int c    = lane & 3;
    const int wm   = wid & 1;
    const int wn   = wid >> 1;
    const int mbase = blockIdx.y * 128;
    const int nbase = blockIdx.x * 128;

    const int lr = tid >> 3;         // 0..31
    const int lc = (tid & 7) << 2;   // 0..28 step 4

    const float* Ap = A + (size_t)(mbase + lr) * DIMV + lc;
    const float* Bp = B + (size_t)(nbase + lr) * DIMV + lc;

    const unsigned smB = smem_u32(sm);
    const unsigned SSZ = STAGE_F * 4;            // stage bytes
    const unsigned stA = smB + (lr * GSTR + lc) * 4;
    const unsigned stB = stA + 128 * GSTR * 4;

    // LDSM per-lane offsets (bytes, within a stage)
    const int lm = lane >> 3, lrr = lane & 7;
    unsigned offA[4], offB[2];
#pragma unroll
    for (int mf = 0; mf < 4; mf++)
        offA[mf] = (unsigned)(((wm * 64 + mf * 16 + (lm & 1) * 8 + lrr) * GSTR
                               + (lm >> 1) * 4) * 4);
#pragma unroll
    for (int p = 0; p < 2; p++)
        offB[p] = (unsigned)((128 * GSTR
                              + (wn * 32 + p * 16 + (lm >> 1) * 8 + lrr) * GSTR
                              + (lm & 1) * 4) * 4);

    float acc[4][4][4];
#pragma unroll
    for (int i = 0; i < 4; i++)
#pragma unroll
        for (int j = 0; j < 4; j++)
#pragma unroll
            for (int e = 0; e < 4; e++) acc[i][j][e] = 0.f;

    auto issue = [&](int t) {
        const unsigned so = (unsigned)(t % 3) * SSZ;
        const float* An = Ap + t * 32;
        const float* Bn = Bp + t * 32;
#pragma unroll
        for (int r = 0; r < 4; r++) {
            CP_ASYNC16(stA + so + r * 32 * GSTR * 4, An + (size_t)r * 32 * DIMV);
            CP_ASYNC16(stB + so + r * 32 * GSTR * 4, Bn + (size_t)r * 32 * DIMV);
        }
        CP_COMMIT();
    };
    issue(0);
    issue(1);

    const int NT = DIMV / 32;
    for (int t = 0; t < NT; t++) {
        if (t + 1 < NT) { CP_WAIT1(); } else { CP_WAIT0(); }
        __syncthreads();               // stage t visible; WAR for buf (t+2)%3
        if (t + 2 < NT) issue(t + 2);

        const unsigned base = smB + (unsigned)(t % 3) * SSZ;
#pragma unroll
        for (int kk = 0; kk < 4; kk++) {
            const unsigned kb = kk * 32;   // 8 floats
            uint32_t a[4][4];
#pragma unroll
            for (int mf = 0; mf < 4; mf++)
                LDSM_X4(a[mf][0], a[mf][1], a[mf][2], a[mf][3],
                        base + offA[mf] + kb);
            uint32_t bfr[2][4];
#pragma unroll
            for (int p = 0; p < 2; p++)
                LDSM_X4(bfr[p][0], bfr[p][1], bfr[p][2], bfr[p][3],
                        base + offB[p] + kb);
#pragma unroll
            for (int nf = 0; nf < 4; nf++) {
                const uint32_t b0 = bfr[nf >> 1][(nf & 1) * 2];
                const uint32_t b1 = bfr[nf >> 1][(nf & 1) * 2 + 1];
#pragma unroll
                for (int mf = 0; mf < 4; mf++) mma8u(acc[mf][nf], a[mf], b0, b1);
            }
        }
    }

    if (mode == 1 || mode == 2) {
        __syncthreads();   // all compute done before reusing pipeline smem
        float* Cs = sm;    // 128 x 132 floats = 67584 B
#pragma unroll
        for (int mf = 0; mf < 4; mf++) {
            const int row = wm * 64 + mf * 16 + g;
#pragma unroll
            for (int nf = 0; nf < 4; nf++) {
                const int col = wn * 32 + nf * 8 + 2 * c;
                *(float2*)&Cs[row * 132 + col] =
                    make_float2(acc[mf][nf][0], acc[mf][nf][1]);
                *(float2*)&Cs[(row + 8) * 132 + col] =
                    make_float2(acc[mf][nf][2], acc[mf][nf][3]);
            }
        }
        __syncthreads();
        const float SC = (mode == 1) ? 0.08838834764831845f : 1.0f;
        for (int p = tid; p < 128 * 32; p += 256) {
            const int r  = p >> 5;
            const int f4 = (p & 31) << 2;
            const int m  = mbase + r;
            const int s  = m & (SEQ - 1);
            const float* crow = &Cs[r * 132];
            float v[4];
            if (f4 < 64) {
#pragma unroll
                for (int e = 0; e < 4; e++) {
                    const int j = f4 + e;
                    const float cs = g_tcos[(s << 6) + j];
                    const float sn = g_tsin[(s << 6) + j];
                    v[e] = tf32r((crow[j] * cs - crow[2 * j + 1] * sn) * SC);
                }
            } else {
#pragma unroll
                for (int e = 0; e < 4; e++) {
                    const int j = f4 - 64 + e;
                    const float cs = g_tcos[(s << 6) + j];
                    const float sn = g_tsin[(s << 6) + j];
                    v[e] = tf32r((crow[j + 64] * cs + crow[2 * j] * sn) * SC);
                }
            }
            *(float4*)&C[(size_t)m * DIMV + nbase + f4] =
                make_float4(v[0], v[1], v[2], v[3]);
        }
    } else {
#pragma unroll
        for (int mf = 0; mf < 4; mf++) {
            const int row = mbase + wm * 64 + mf * 16 + g;
#pragma unroll
            for (int nf = 0; nf < 4; nf++) {
                const int col = nbase + wn * 32 + nf * 8 + 2 * c;
                float o0 = acc[mf][nf][0], o1 = acc[mf][nf][1];
                float o2 = acc[mf][nf][2], o3 = acc[mf][nf][3];
                if (mode == 3) {
                    o0 = tf32r(o0); o1 = tf32r(o1);
                    o2 = tf32r(o2); o3 = tf32r(o3);
                }
                *(float2*)&C[(size_t)row * DIMV + col] = make_float2(o0, o1);
                *(float2*)&C[(size_t)(row + 8) * DIMV + col] = make_float2(o2, o3);
            }
        }
    }
}

// ---------------------------------------------------------------------------
// Causal flash attention. One block = 64 query rows of one (b,h); 4 warps.
// Bkv=64, cp.async split commit groups (V hidden behind S+softmax), P aliases
// the K region, __expf softmax, LDSM fragment loads for Q/K/P.
// Smem 102400 B -> 2 CTAs/SM.
// ---------------------------------------------------------------------------
#define QSTR 132
#define KSTR 132
#define VSTR 136
#define PSTR 68
#define KOFS (64 * QSTR)
#define VOFS (KOFS + 64 * KSTR)
#define FLASH_SMEM ((VOFS + 64 * VSTR) * 4)   // 102400

__global__ __launch_bounds__(128) void flash_kernel() {
    extern __shared__ float sm[];
    float* Qs = sm;
    float* Ks = sm + KOFS;     // re-used as P after the S phase
    float* Vs = sm + VOFS;

    const int tid  = threadIdx.x;
    const int lane = tid & 31;
    const int w    = tid >> 5;
    const int g    = lane >> 2;
    const int c    = lane & 3;

    const int qt = (int)gridDim.x - 1 - (int)blockIdx.x;  // heavy tiles first
    const int h  = blockIdx.y;
    const int b  = blockIdx.z;
    const int q0 = qt * 64;
    const size_t brow = (size_t)b * SEQ;
    const int hcol = h * HDIM;

    const unsigned smB = smem_u32(sm);
    const int lm = lane >> 3, lrr = lane & 7;
    const unsigned offQ = (unsigned)(((w * 16 + (lm & 1) * 8 + lrr) * QSTR
                                      + (lm >> 1) * 4) * 4);
    unsigned offK[4];
#pragma unroll
    for (int p = 0; p < 4; p++)
        offK[p] = (unsigned)((KOFS + (p * 16 + (lm >> 1) * 8 + lrr) * KSTR
                              + (lm & 1) * 4) * 4);
    const unsigned offP = (unsigned)((KOFS + w * 16 * PSTR
                                      + ((lm & 1) * 8 + lrr) * PSTR
                                      + (lm >> 1) * 4) * 4);

    // Stage Q once (pre-rounded, scale folded in)
    for (int idx = tid; idx < 64 * 32; idx += 128) {
        int r = idx >> 5, d4 = (idx & 31) << 2;
        CP_ASYNC16(smem_u32(&Qs[r * QSTR + d4]),
                   &g_qr[(brow + q0 + r) * DIMV + hcol + d4]);
    }
    CP_COMMIT();

    float O[16][4];
#pragma unroll
    for (int nf = 0; nf < 16; nf++)
#pragma unroll
        for (int e = 0; e < 4; e++) O[nf][e] = 0.f;
    float m0 = -1e30f, m1 = -1e30f, l0 = 0.f, l1 = 0.f;
    float* Pw = Ks + w * 16 * PSTR;   // alias into K region

    for (int kt = 0; kt <= qt; kt++) {
        __syncthreads();   // prior iter's P/V reads done before restaging
        for (int idx = tid; idx < 64 * 32; idx += 128) {
            int r = idx >> 5, d4 = (idx & 31) << 2;
            CP_ASYNC16(smem_u32(&Ks[r * KSTR + d4]),
                       &g_kr[(brow + (size_t)kt * 64 + r) * DIMV + hcol + d4]);
        }
        CP_COMMIT();
        for (int idx = tid; idx < 64 * 32; idx += 128) {
            int r = idx >> 5, d4 = (idx & 31) << 2;
            CP_ASYNC16(smem_u32(&Vs[r * VSTR + d4]),
                       &g_v[(brow + (size_t)kt * 64 + r) * DIMV + hcol + d4]);
        }
        CP_COMMIT();
        CP_WAIT1();        // K (and Q on first iter) landed; V in flight
        __syncthreads();

        // ---- S = Q K^T (16 x 64 per warp), LDSM-fed ----
        float sacc[8][4];
#pragma unroll
        for (int nf = 0; nf < 8; nf++)
#pragma unroll
            for (int e = 0; e < 4; e++) sacc[nf][e] = 0.f;

#pragma unroll
        for (int k0 = 0; k0 < 128; k0 += 8) {
            uint32_t a[4];
            LDSM_X4(a[0], a[1], a[2], a[3], smB + offQ + k0 * 4);
            uint32_t kb[4][4];
#pragma unroll
            for (int p = 0; p < 4; p++)
                LDSM_X4(kb[p][0], kb[p][1], kb[p][2], kb[p][3],
                        smB + offK[p] + k0 * 4);
#pragma unroll
            for (int nf = 0; nf < 8; nf++)
                mma8u(sacc[nf], a, kb[nf >> 1][(nf & 1) * 2],
                      kb[nf >> 1][(nf & 1) * 2 + 1]);
        }

        // Causal mask on the diagonal tile (local coords)
        if (kt == qt) {
            const int r0 = w * 16 + g;
#pragma unroll
            for (int nf = 0; nf < 8; nf++) {
                const int col0 = nf * 8 + 2 * c;
                if (col0     > r0)     sacc[nf][0] = -1e30f;
                if (col0 + 1 > r0)     sacc[nf][1] = -1e30f;
                if (col0     > r0 + 8) sacc[nf][2] = -1e30f;
                if (col0 + 1 > r0 + 8) sacc[nf][3] = -1e30f;
            }
        }

        // Row max (in-thread + quad shuffle)
        float rm0 = -1e30f, rm1 = -1e30f;
#pragma unroll
        for (int nf = 0; nf < 8; nf++) {
            rm0 = fmaxf(rm0, fmaxf(sacc[nf][0], sacc[nf][1]));
            rm1 = fmaxf(rm1, fmaxf(sacc[nf][2], sacc[nf][3]));
        }
        rm0 = fmaxf(rm0, __shfl_xor_sync(0xffffffffu, rm0, 1));
        rm0 = fmaxf(rm0, __shfl_xor_sync(0xffffffffu, rm0, 2));
        rm1 = fmaxf(rm1, __shfl_xor_sync(0xffffffffu, rm1, 1));
        rm1 = fmaxf(rm1, __shfl_xor_sync(0xffffffffu, rm1, 2));

        const float mn0 = fmaxf(m0, rm0), mn1 = fmaxf(m1, rm1);
        const float al0 = __expf(m0 - mn0), al1 = __expf(m1 - mn1);

        float ps0 = 0.f, ps1 = 0.f;
#pragma unroll
        for (int nf = 0; nf < 8; nf++) {
            sacc[nf][0] = __expf(sacc[nf][0] - mn0);
            sacc[nf][1] = __expf(sacc[nf][1] - mn0);
            sacc[nf][2] = __expf(sacc[nf][2] - mn1);
            sacc[nf][3] = __expf(sacc[nf][3] - mn1);
            ps0 += sacc[nf][0] + sacc[nf][1];
            ps1 += sacc[nf][2] + sacc[nf][3];
        }
        ps0 += __shfl_xor_sync(0xffffffffu, ps0, 1);
        ps0 += __shfl_xor_sync(0xffffffffu, ps0, 2);
        ps1 += __shfl_xor_sync(0xffffffffu, ps1, 1);
        ps1 += __shfl_xor_sync(0xffffffffu, ps1, 2);
        l0 = l0 * al0 + ps0;
        l1 = l1 * al1 + ps1;
        m0 = mn0; m1 = mn1;

#pragma unroll
        for (int nf = 0; nf < 16; nf++) {
            O[nf][0] *= al0; O[nf][1] *= al0;
            O[nf][2] *= al1; O[nf][3] *= al1;
        }

        CP_WAIT0();        // V landed
        __syncthreads();   // all warps done READING K before P overwrites

        // P: C-layout -> per-warp smem slice (K region) -> A-layout
#pragma unroll
        for (int nf = 0; nf < 8; nf++) {
            const int col = nf * 8 + 2 * c;
            *(float2*)&Pw[g * PSTR + col] =
                make_float2(tf32r(sacc[nf][0]), tf32r(sacc[nf][1]));
            *(float2*)&Pw[(g + 8) * PSTR + col] =
                make_float2(tf32r(sacc[nf][2]), tf32r(sacc[nf][3]));
        }
        __syncwarp();

        // ---- O += P V ---- (P via LDSM, V scalar: pattern is transposed)
#pragma unroll
        for (int k0 = 0; k0 < 64; k0 += 8) {
            uint32_t a[4];
            LDSM_X4(a[0], a[1], a[2], a[3], smB + offP + k0 * 4);
#pragma unroll
            for (int nf = 0; nf < 16; nf++) {
                const uint32_t b0 =
                    __float_as_uint(Vs[(k0 + c) * VSTR + nf * 8 + g]);
                const uint32_t b1 =
                    __float_as_uint(Vs[(k0 + c + 4) * VSTR + nf * 8 + g]);
                mma8u(O[nf], a, b0, b1);
            }
        }
    }

    // Epilogue: normalize, tf32-round (feeds the Wo GEMM), write [B,S,H*D]
    const float r0 = 1.f / l0, r1 = 1.f / l1;
    const int qrow = q0 + w * 16 + g;
#pragma unroll
    for (int nf = 0; nf < 16; nf++) {
        const int col = hcol + nf * 8 + 2 * c;
        *(float2*)&g_att[(brow + qrow) * DIMV + col] =
            make_float2(tf32r(O[nf][0] * r0), tf32r(O[nf][1] * r0));
        *(float2*)&g_att[(brow + qrow + 8) * DIMV + col] =
            make_float2(tf32r(O[nf][2] * r1), tf32r(O[nf][3] * r1));
    }
}

// ---------------------------------------------------------------------------
// Launch. 6 launches; ncu (-s 5 -c 1) captures the Wo GEMM.
// ---------------------------------------------------------------------------
extern "C" void kernel_launch(void* const* d_in, const int* in_sizes, int n_in,
                              void* d_out, int out_size) {
    (void)in_sizes; (void)n_in; (void)out_size;
    const float* x  = (const float*)d_in[0];
    const float* Wq = (const float*)d_in[1];
    const float* Wk = (const float*)d_in[2];
    const float* Wv = (const float*)d_in[3];
    const float* Wo = (const float*)d_in[4];
    float* out = (float*)d_out;

    float *pqr, *pkr, *pv, *patt, *pxr, *pwq, *pwk, *pwv, *pwo;
    cudaGetSymbolAddress((void**)&pqr,  g_qr);
    cudaGetSymbolAddress((void**)&pkr,  g_kr);
    cudaGetSymbolAddress((void**)&pv,   g_v);
    cudaGetSymbolAddress((void**)&patt, g_att);
    cudaGetSymbolAddress((void**)&pxr,  g_xr);
    cudaGetSymbolAddress((void**)&pwq,  g_wqr);
    cudaGetSymbolAddress((void**)&pwk,  g_wkr);
    cudaGetSymbolAddress((void**)&pwv,  g_wvr);
    cudaGetSymbolAddress((void**)&pwo,  g_wor);

    cudaFuncSetAttribute(gemm_nt,
                         cudaFuncAttributeMaxDynamicSharedMemorySize, GEMM_SMEM);
    cudaFuncSetAttribute(flash_kernel,
                         cudaFuncAttributeMaxDynamicSharedMemorySize, FLASH_SMEM);

    round_all<<<(NALL4 + 1023) / 1024, 256>>>(x, Wq, Wk, Wv, Wo);
    invf_kernel<<<1, 64>>>();
    rope_tables<<<(SEQ * 64 + 255) / 256, 256>>>();

    dim3 gq(DIMV / 128, GM / 128, 3);   // Q,K,V fused
    gemm_nt<<<gq, 256, GEMM_SMEM>>>(pxr, pwq, pwk, pwv, pqr, pkr, pv, 1, 2, 3);
    flash_kernel<<<dim3(SEQ / 64, NHEAD, 2), 128, FLASH_SMEM>>>();
    dim3 go(DIMV / 128, GM / 128, 1);   // output projection (ncu capture slot)
    gemm_nt<<<go, 256, GEMM_SMEM>>>(patt, pwo, pwo, pwo, out, out, out, 0, 0, 0);
}